// round 2
// baseline (speedup 1.0000x reference)
#include <cuda_runtime.h>
#include <math.h>

// Problem constants
static constexpr int NN   = 10000;          // nodes
static constexpr int EE   = 320000;         // edges
static constexpr int EN   = EE + NN;        // edges + self loops
static constexpr int IND  = 512;
static constexpr int HIDD = 128;
static constexpr int OUTD = 128;
static constexpr int HEADS = 4;
static constexpr int GC    = 64;
static constexpr int FEAT  = HEADS * GC;    // 256
static constexpr float NEG_SLOPE = 0.2f;

// -------- scratch (device globals: no allocation allowed) --------
__device__ float d_h1[(size_t)NN * HIDD];
__device__ float d_h2[(size_t)NN * OUTD];
__device__ float d_g [(size_t)NN * FEAT];
__device__ float d_asrc[NN * HEADS];
__device__ float d_adst[NN * HEADS];
__device__ float d_ebuf[(size_t)EN * HEADS];
__device__ float d_m[NN * HEADS];
__device__ float d_s[NN * HEADS];
__device__ int   d_is64;

// -------- helpers --------
__device__ __forceinline__ float atomicMaxFloat(float* addr, float value) {
    int* ai = (int*)addr;
    int old = *ai;
    while (__int_as_float(old) < value) {
        int assumed = old;
        old = atomicCAS(ai, assumed, __float_as_int(value));
        if (old == assumed) break;
    }
    return __int_as_float(old);
}

__device__ __forceinline__ void load_edge(const void* ei, int is64, int tid,
                                          int& s, int& d) {
    if (tid < EE) {
        if (is64) {
            const long long* p = (const long long*)ei;
            s = (int)p[tid];
            d = (int)p[EE + tid];
        } else {
            const int* p = (const int*)ei;
            s = p[tid];
            d = p[EE + tid];
        }
    } else {
        s = d = tid - EE;
    }
}

// Detect int64 vs int32 edge_index: int64 values < 10000 => every odd 32-bit
// word is zero; random int32 node ids make that essentially impossible.
__global__ void detect_kernel(const int* ei) {
    int ok64 = 1;
    for (int i = 1; i < 256; i += 2)
        if (ei[i] != 0) { ok64 = 0; break; }
    d_is64 = ok64;
}

// -------- tiled fp32 GEMM: C[M,Nc] = A[M,K] @ B[K,Nc] (+bias)(+relu) --------
// BM=64, BN=64, BK=16, 256 threads, 4x4 micro-tile per thread.
// Requires: K % 16 == 0, Nc % 64 == 0 (true for all three GEMMs here).
__global__ void gemm_bias_act(const float* __restrict__ A,
                              const float* __restrict__ B,
                              const float* __restrict__ bias,
                              float* __restrict__ C,
                              int M, int Nc, int K, int do_relu) {
    __shared__ float As[64][17];   // padded: conflict-free column reads
    __shared__ float Bs[16][64];

    const int t  = threadIdx.x;
    const int tx = t & 15;
    const int ty = t >> 4;
    const int m0 = blockIdx.y * 64;
    const int n0 = blockIdx.x * 64;

    const int aRow = t >> 2;          // 0..63
    const int aCol = (t & 3) * 4;     // 0,4,8,12
    const int bRow = t >> 4;          // 0..15
    const int bCol = (t & 15) * 4;    // 0..60

    float acc[4][4] = {};

    for (int k0 = 0; k0 < K; k0 += 16) {
        if (m0 + aRow < M) {
            float4 v = *(const float4*)&A[(size_t)(m0 + aRow) * K + k0 + aCol];
            As[aRow][aCol + 0] = v.x; As[aRow][aCol + 1] = v.y;
            As[aRow][aCol + 2] = v.z; As[aRow][aCol + 3] = v.w;
        } else {
            As[aRow][aCol + 0] = 0.f; As[aRow][aCol + 1] = 0.f;
            As[aRow][aCol + 2] = 0.f; As[aRow][aCol + 3] = 0.f;
        }
        {
            float4 v = *(const float4*)&B[(size_t)(k0 + bRow) * Nc + n0 + bCol];
            Bs[bRow][bCol + 0] = v.x; Bs[bRow][bCol + 1] = v.y;
            Bs[bRow][bCol + 2] = v.z; Bs[bRow][bCol + 3] = v.w;
        }
        __syncthreads();

        #pragma unroll
        for (int k = 0; k < 16; k++) {
            float a[4], b[4];
            #pragma unroll
            for (int i = 0; i < 4; i++) a[i] = As[ty * 4 + i][k];
            #pragma unroll
            for (int j = 0; j < 4; j++) b[j] = Bs[k][tx * 4 + j];
            #pragma unroll
            for (int i = 0; i < 4; i++)
                #pragma unroll
                for (int j = 0; j < 4; j++)
                    acc[i][j] = fmaf(a[i], b[j], acc[i][j]);
        }
        __syncthreads();
    }

    #pragma unroll
    for (int i = 0; i < 4; i++) {
        int row = m0 + ty * 4 + i;
        if (row >= M) continue;
        #pragma unroll
        for (int j = 0; j < 4; j++) {
            int col = n0 + tx * 4 + j;
            float v = acc[i][j];
            if (bias) v += bias[col];
            if (do_relu) v = fmaxf(v, 0.f);
            C[(size_t)row * Nc + col] = v;
        }
    }
}

// -------- per-node attention coefficients: one warp per (node, head) --------
__global__ void attn_coef_kernel(const float* __restrict__ att_src,
                                 const float* __restrict__ att_dst) {
    int warp = (blockIdx.x * blockDim.x + threadIdx.x) >> 5;
    int lane = threadIdx.x & 31;
    if (warp >= NN * HEADS) return;
    int n = warp / HEADS, h = warp % HEADS;
    const float* gp = d_g + (size_t)n * FEAT + h * GC;
    float ss = 0.f, sd = 0.f;
    #pragma unroll
    for (int c = lane; c < GC; c += 32) {
        float gv = gp[c];
        ss += gv * att_src[h * GC + c];
        sd += gv * att_dst[h * GC + c];
    }
    #pragma unroll
    for (int o = 16; o; o >>= 1) {
        ss += __shfl_xor_sync(0xFFFFFFFFu, ss, o);
        sd += __shfl_xor_sync(0xFFFFFFFFu, sd, o);
    }
    if (lane == 0) {
        d_asrc[n * HEADS + h] = ss;
        d_adst[n * HEADS + h] = sd;
    }
}

// -------- init: m = -inf-ish, s = 0, out = bias broadcast --------
__global__ void init_ms_kernel() {
    int tid = blockIdx.x * blockDim.x + threadIdx.x;
    if (tid < NN * HEADS) { d_m[tid] = -1e30f; d_s[tid] = 0.f; }
}
__global__ void init_out_kernel(float* __restrict__ out,
                                const float* __restrict__ bias_g) {
    int tid = blockIdx.x * blockDim.x + threadIdx.x;
    if (tid < NN * FEAT) out[tid] = bias_g[tid & (FEAT - 1)];
}

// -------- edge pass 1: e = leaky(a_src[s]+a_dst[d]); segment max --------
__global__ void edge_pass1(const void* __restrict__ ei) {
    int tid = blockIdx.x * blockDim.x + threadIdx.x;
    if (tid >= EN) return;
    int s, d;
    load_edge(ei, d_is64, tid, s, d);
    #pragma unroll
    for (int h = 0; h < HEADS; h++) {
        float e = d_asrc[s * HEADS + h] + d_adst[d * HEADS + h];
        e = (e > 0.f) ? e : NEG_SLOPE * e;
        d_ebuf[(size_t)tid * HEADS + h] = e;
        atomicMaxFloat(&d_m[d * HEADS + h], e);
    }
}

// -------- edge pass 2: ex = exp(e - m[d]); segment sum --------
__global__ void edge_pass2(const void* __restrict__ ei) {
    int tid = blockIdx.x * blockDim.x + threadIdx.x;
    if (tid >= EN) return;
    int s, d;
    load_edge(ei, d_is64, tid, s, d);
    #pragma unroll
    for (int h = 0; h < HEADS; h++) {
        float ex = __expf(d_ebuf[(size_t)tid * HEADS + h] - d_m[d * HEADS + h]);
        d_ebuf[(size_t)tid * HEADS + h] = ex;
        atomicAdd(&d_s[d * HEADS + h], ex);
    }
}

// -------- edge pass 3: out[d] += alpha * g[s]  (4 channels / thread) --------
__global__ void edge_pass3(const void* __restrict__ ei,
                           float* __restrict__ out) {
    int tid = blockIdx.x * blockDim.x + threadIdx.x;   // EN*64 threads
    if (tid >= EN * 64) return;
    int edge = tid >> 6;
    int q    = tid & 63;          // quad index within feature row
    int h    = q >> 4;            // 16 quads per head
    int c    = q * 4;
    int s, d;
    load_edge(ei, d_is64, edge, s, d);
    float alpha = d_ebuf[(size_t)edge * HEADS + h] / d_s[d * HEADS + h];
    float4 gv = *(const float4*)&d_g[(size_t)s * FEAT + c];
    float* op = &out[(size_t)d * FEAT + c];
    atomicAdd(op + 0, gv.x * alpha);
    atomicAdd(op + 1, gv.y * alpha);
    atomicAdd(op + 2, gv.z * alpha);
    atomicAdd(op + 3, gv.w * alpha);
}

// ----------------------------------------------------------------------------
extern "C" void kernel_launch(void* const* d_in, const int* in_sizes, int n_in,
                              void* d_out, int out_size) {
    const float* x        = (const float*)d_in[0];
    const void*  ei       = d_in[1];
    const float* W1       = (const float*)d_in[2];
    const float* b1       = (const float*)d_in[3];
    const float* W2       = (const float*)d_in[4];
    const float* b2       = (const float*)d_in[5];
    const float* Wg       = (const float*)d_in[6];
    const float* att_src  = (const float*)d_in[7];
    const float* att_dst  = (const float*)d_in[8];
    const float* bias_g   = (const float*)d_in[9];
    float* out = (float*)d_out;

    void *p_h1, *p_h2, *p_g;
    cudaGetSymbolAddress(&p_h1, d_h1);
    cudaGetSymbolAddress(&p_h2, d_h2);
    cudaGetSymbolAddress(&p_g,  d_g);

    detect_kernel<<<1, 1>>>((const int*)ei);

    // encoder: h1 = relu(x@W1 + b1) ; h2 = h1@W2 + b2 ; g = h2@Wg
    {
        dim3 grid(HIDD / 64, (NN + 63) / 64);
        gemm_bias_act<<<grid, 256>>>(x, W1, b1, (float*)p_h1, NN, HIDD, IND, 1);
    }
    {
        dim3 grid(OUTD / 64, (NN + 63) / 64);
        gemm_bias_act<<<grid, 256>>>((const float*)p_h1, W2, b2, (float*)p_h2,
                                     NN, OUTD, HIDD, 0);
    }
    {
        dim3 grid(FEAT / 64, (NN + 63) / 64);
        gemm_bias_act<<<grid, 256>>>((const float*)p_h2, Wg, nullptr, (float*)p_g,
                                     NN, FEAT, OUTD, 0);
    }

    // attention coefficients (one warp per node-head)
    {
        int warps = NN * HEADS;
        int blocks = (warps * 32 + 255) / 256;
        attn_coef_kernel<<<blocks, 256>>>(att_src, att_dst);
    }

    // init segment-max / segment-sum / output bias
    init_ms_kernel<<<(NN * HEADS + 255) / 256, 256>>>();
    init_out_kernel<<<(NN * FEAT + 255) / 256, 256>>>(out, bias_g);

    // edge phase
    {
        int blocks = (EN + 255) / 256;
        edge_pass1<<<blocks, 256>>>(ei);
        edge_pass2<<<blocks, 256>>>(ei);
    }
    {
        int total = EN * 64;
        edge_pass3<<<(total + 255) / 256, 256>>>(ei, out);
    }
}

// round 3
// speedup vs baseline: 2.0631x; 2.0631x over previous
#include <cuda_runtime.h>
#include <math.h>

// Problem constants
static constexpr int NN   = 10000;
static constexpr int EE   = 320000;
static constexpr int EN   = EE + NN;        // edges + self loops
static constexpr int IND  = 512;
static constexpr int HIDD = 128;
static constexpr int OUTD = 128;
static constexpr int HEADS = 4;
static constexpr int GC    = 64;
static constexpr int FEAT  = HEADS * GC;    // 256
static constexpr float NEG_SLOPE = 0.2f;
static constexpr int MAXDEG = 256;          // shared-mem cache cap (deg ~ Poisson(33))

// -------- scratch (device globals: no allocation allowed) --------
__device__ float d_h1[(size_t)NN * HIDD];
__device__ float d_h2[(size_t)NN * OUTD];
__device__ float d_g [(size_t)NN * FEAT];
__device__ float d_asrc[NN * HEADS];
__device__ float d_adst[NN * HEADS];
__device__ int   d_cnt[NN];          // histogram, then reused as fill cursor
__device__ int   d_off[NN + 1];      // CSR offsets
__device__ int   d_src_csr[EN];      // src node per CSR slot
__device__ int   d_is64;

// -------- helpers --------
__device__ __forceinline__ void load_edge(const void* ei, int is64, int tid,
                                          int& s, int& d) {
    if (tid < EE) {
        if (is64) {
            const long long* p = (const long long*)ei;
            s = (int)p[tid];
            d = (int)p[EE + tid];
        } else {
            const int* p = (const int*)ei;
            s = p[tid];
            d = p[EE + tid];
        }
    } else {
        s = d = tid - EE;
    }
}

// Detect int64 vs int32 edge_index (int64 node ids < 10000 => odd words all 0)
__global__ void detect_kernel(const int* ei) {
    int ok64 = 1;
    for (int i = 1; i < 256; i += 2)
        if (ei[i] != 0) { ok64 = 0; break; }
    d_is64 = ok64;
}

// -------- tiled fp32 GEMM: C[M,Nc] = A[M,K] @ B[K,Nc] (+bias)(+relu) --------
__global__ void gemm_bias_act(const float* __restrict__ A,
                              const float* __restrict__ B,
                              const float* __restrict__ bias,
                              float* __restrict__ C,
                              int M, int Nc, int K, int do_relu) {
    __shared__ float As[64][17];
    __shared__ float Bs[16][64];

    const int t  = threadIdx.x;
    const int tx = t & 15;
    const int ty = t >> 4;
    const int m0 = blockIdx.y * 64;
    const int n0 = blockIdx.x * 64;

    const int aRow = t >> 2;
    const int aCol = (t & 3) * 4;
    const int bRow = t >> 4;
    const int bCol = (t & 15) * 4;

    float acc[4][4] = {};

    for (int k0 = 0; k0 < K; k0 += 16) {
        if (m0 + aRow < M) {
            float4 v = *(const float4*)&A[(size_t)(m0 + aRow) * K + k0 + aCol];
            As[aRow][aCol + 0] = v.x; As[aRow][aCol + 1] = v.y;
            As[aRow][aCol + 2] = v.z; As[aRow][aCol + 3] = v.w;
        } else {
            As[aRow][aCol + 0] = 0.f; As[aRow][aCol + 1] = 0.f;
            As[aRow][aCol + 2] = 0.f; As[aRow][aCol + 3] = 0.f;
        }
        {
            float4 v = *(const float4*)&B[(size_t)(k0 + bRow) * Nc + n0 + bCol];
            Bs[bRow][bCol + 0] = v.x; Bs[bRow][bCol + 1] = v.y;
            Bs[bRow][bCol + 2] = v.z; Bs[bRow][bCol + 3] = v.w;
        }
        __syncthreads();

        #pragma unroll
        for (int k = 0; k < 16; k++) {
            float a[4], b[4];
            #pragma unroll
            for (int i = 0; i < 4; i++) a[i] = As[ty * 4 + i][k];
            #pragma unroll
            for (int j = 0; j < 4; j++) b[j] = Bs[k][tx * 4 + j];
            #pragma unroll
            for (int i = 0; i < 4; i++)
                #pragma unroll
                for (int j = 0; j < 4; j++)
                    acc[i][j] = fmaf(a[i], b[j], acc[i][j]);
        }
        __syncthreads();
    }

    #pragma unroll
    for (int i = 0; i < 4; i++) {
        int row = m0 + ty * 4 + i;
        if (row >= M) continue;
        #pragma unroll
        for (int j = 0; j < 4; j++) {
            int col = n0 + tx * 4 + j;
            float v = acc[i][j];
            if (bias) v += bias[col];
            if (do_relu) v = fmaxf(v, 0.f);
            C[(size_t)row * Nc + col] = v;
        }
    }
}

// -------- per-node attention coefficients: one warp per (node, head) --------
__global__ void attn_coef_kernel(const float* __restrict__ att_src,
                                 const float* __restrict__ att_dst) {
    int warp = (blockIdx.x * blockDim.x + threadIdx.x) >> 5;
    int lane = threadIdx.x & 31;
    if (warp >= NN * HEADS) return;
    int n = warp / HEADS, h = warp % HEADS;
    const float* gp = d_g + (size_t)n * FEAT + h * GC;
    float ss = 0.f, sd = 0.f;
    #pragma unroll
    for (int c = lane; c < GC; c += 32) {
        float gv = gp[c];
        ss += gv * att_src[h * GC + c];
        sd += gv * att_dst[h * GC + c];
    }
    #pragma unroll
    for (int o = 16; o; o >>= 1) {
        ss += __shfl_xor_sync(0xFFFFFFFFu, ss, o);
        sd += __shfl_xor_sync(0xFFFFFFFFu, sd, o);
    }
    if (lane == 0) {
        d_asrc[n * HEADS + h] = ss;
        d_adst[n * HEADS + h] = sd;
    }
}

// -------- CSR build --------
__global__ void zero_cnt_kernel() {
    int tid = blockIdx.x * blockDim.x + threadIdx.x;
    if (tid < NN) d_cnt[tid] = 0;
}

__global__ void count_kernel(const void* __restrict__ ei) {
    int tid = blockIdx.x * blockDim.x + threadIdx.x;
    if (tid >= EN) return;
    int s, d;
    load_edge(ei, d_is64, tid, s, d);
    atomicAdd(&d_cnt[d], 1);
}

// single block of 1024 threads: exclusive scan of d_cnt -> d_off, zero d_cnt
__global__ void scan_kernel() {
    __shared__ int part[1024];
    const int t = threadIdx.x;
    const int CH = (NN + 1023) / 1024;   // 10
    const int base = t * CH;
    int sum = 0;
    for (int i = 0; i < CH; i++) {
        int idx = base + i;
        if (idx < NN) sum += d_cnt[idx];
    }
    part[t] = sum;
    __syncthreads();
    for (int o = 1; o < 1024; o <<= 1) {
        int v = 0;
        if (t >= o) v = part[t - o];
        __syncthreads();
        if (t >= o) part[t] += v;
        __syncthreads();
    }
    int run = (t == 0) ? 0 : part[t - 1];
    for (int i = 0; i < CH; i++) {
        int idx = base + i;
        if (idx < NN) {
            d_off[idx] = run;
            run += d_cnt[idx];
            d_cnt[idx] = 0;          // reset for use as fill cursor
        }
    }
    if (t == 1023) d_off[NN] = part[1023];
}

__global__ void fill_kernel(const void* __restrict__ ei) {
    int tid = blockIdx.x * blockDim.x + threadIdx.x;
    if (tid >= EN) return;
    int s, d;
    load_edge(ei, d_is64, tid, s, d);
    int pos = atomicAdd(&d_cnt[d], 1);
    d_src_csr[d_off[d] + pos] = s;
}

// -------- gather aggregation: 64 threads per node, 4 nodes per block --------
// Each thread owns channel quad c = 4*t (head h = t>>4). Softmax sums per head
// are computed cooperatively (16 lanes per head), ex cached in shared.
__global__ void __launch_bounds__(256) gather_kernel(float* __restrict__ out,
                                                     const float* __restrict__ bias_g) {
    __shared__ float s_ex[4][MAXDEG * HEADS];
    __shared__ int   s_src[4][MAXDEG];

    const int grp  = threadIdx.x >> 6;       // 0..3: node slot in block
    const int t    = threadIdx.x & 63;       // 0..63: channel quad owner
    const int node = blockIdx.x * 4 + grp;   // NN = 10000 divisible by 4
    const int h    = t >> 4;                 // head of my channels
    const int l16  = t & 15;

    const int beg = d_off[node];
    const int deg = d_off[node + 1] - beg;
    const int cached = (deg < MAXDEG) ? deg : MAXDEG;

    // stage src ids into shared
    for (int j = t; j < cached; j += 64)
        s_src[grp][j] = d_src_csr[beg + j];
    __syncthreads();

    const float adst_h = d_adst[node * HEADS + h];

    // pass 1: ex per (edge, my head), partial softmax sum over 16 lanes
    float psum = 0.f;
    for (int j = l16; j < deg; j += 16) {
        int s = (j < MAXDEG) ? s_src[grp][j] : d_src_csr[beg + j];
        float e = d_asrc[s * HEADS + h] + adst_h;
        e = (e > 0.f) ? e : NEG_SLOPE * e;
        float ex = __expf(e);
        if (j < MAXDEG) s_ex[grp][j * HEADS + h] = ex;
        psum += ex;
    }
    #pragma unroll
    for (int o = 8; o; o >>= 1)
        psum += __shfl_xor_sync(0xFFFFFFFFu, psum, o);
    const float inv = __frcp_rn(psum);       // deg >= 1 (self loop)
    __syncthreads();

    // pass 2: accumulate alpha-weighted g[src] rows
    float4 acc = make_float4(0.f, 0.f, 0.f, 0.f);
    for (int j = 0; j < deg; j++) {
        float ex;
        int s;
        if (j < MAXDEG) {
            ex = s_ex[grp][j * HEADS + h];
            s  = s_src[grp][j];
        } else {
            s = d_src_csr[beg + j];
            float e = d_asrc[s * HEADS + h] + adst_h;
            e = (e > 0.f) ? e : NEG_SLOPE * e;
            ex = __expf(e);
        }
        float alpha = ex * inv;
        float4 gv = *(const float4*)&d_g[(size_t)s * FEAT + 4 * t];
        acc.x = fmaf(gv.x, alpha, acc.x);
        acc.y = fmaf(gv.y, alpha, acc.y);
        acc.z = fmaf(gv.z, alpha, acc.z);
        acc.w = fmaf(gv.w, alpha, acc.w);
    }

    float4 bv = *(const float4*)&bias_g[4 * t];
    acc.x += bv.x; acc.y += bv.y; acc.z += bv.z; acc.w += bv.w;
    *(float4*)&out[(size_t)node * FEAT + 4 * t] = acc;
}

// ----------------------------------------------------------------------------
extern "C" void kernel_launch(void* const* d_in, const int* in_sizes, int n_in,
                              void* d_out, int out_size) {
    const float* x        = (const float*)d_in[0];
    const void*  ei       = d_in[1];
    const float* W1       = (const float*)d_in[2];
    const float* b1       = (const float*)d_in[3];
    const float* W2       = (const float*)d_in[4];
    const float* b2       = (const float*)d_in[5];
    const float* Wg       = (const float*)d_in[6];
    const float* att_src  = (const float*)d_in[7];
    const float* att_dst  = (const float*)d_in[8];
    const float* bias_g   = (const float*)d_in[9];
    float* out = (float*)d_out;

    void *p_h1, *p_h2, *p_g;
    cudaGetSymbolAddress(&p_h1, d_h1);
    cudaGetSymbolAddress(&p_h2, d_h2);
    cudaGetSymbolAddress(&p_g,  d_g);

    detect_kernel<<<1, 1>>>((const int*)ei);

    // CSR build (independent of GEMM chain, but same stream is fine)
    zero_cnt_kernel<<<(NN + 255) / 256, 256>>>();
    count_kernel<<<(EN + 255) / 256, 256>>>(ei);
    scan_kernel<<<1, 1024>>>();
    fill_kernel<<<(EN + 255) / 256, 256>>>(ei);

    // encoder: h1 = relu(x@W1 + b1) ; h2 = h1@W2 + b2 ; g = h2@Wg
    {
        dim3 grid(HIDD / 64, (NN + 63) / 64);
        gemm_bias_act<<<grid, 256>>>(x, W1, b1, (float*)p_h1, NN, HIDD, IND, 1);
    }
    {
        dim3 grid(OUTD / 64, (NN + 63) / 64);
        gemm_bias_act<<<grid, 256>>>((const float*)p_h1, W2, b2, (float*)p_h2,
                                     NN, OUTD, HIDD, 0);
    }
    {
        dim3 grid(FEAT / 64, (NN + 63) / 64);
        gemm_bias_act<<<grid, 256>>>((const float*)p_h2, Wg, nullptr, (float*)p_g,
                                     NN, FEAT, OUTD, 0);
    }

    // attention coefficients
    {
        int warps = NN * HEADS;
        attn_coef_kernel<<<(warps * 32 + 255) / 256, 256>>>(att_src, att_dst);
    }

    // softmax + aggregation, gather-based (no output atomics)
    gather_kernel<<<NN / 4, 256>>>(out, bias_g);
}